// round 16
// baseline (speedup 1.0000x reference)
#include <cuda_runtime.h>
#include <cuda_fp16.h>

// Problem constants
#define B_ 8
#define S_ 1024
#define D_ 256
#define NR (B_*S_)   // 8192 rows

// Scratch (static device allocations — allowed)
// A-side: fp16 {hi,lo} per value-pair -> uint2 {hi_f16x2, lo_f16x2} per k-pair
__device__ __align__(16) uint2    g_xs [NR*128];      // X split
__device__ __align__(16) uint2    g_xqs[NR*128];      // rope(q) split
__device__ __align__(16) uint2    g_xvs[NR*128];      // rope(v) split
// B-side: single fp16 plane, 1 unsigned (f16x2) per k-pair
__device__ __align__(16) unsigned g_wq1[D_*128];      // Wq fp16
__device__ __align__(16) unsigned g_wv1[D_*128];      // Wv fp16
__device__ __align__(16) unsigned g_w2f[B_*D_*128];   // W2^T fp16 [b][n][kpair]

// ---------------------------------------------------------------------------
// fp16 2-term: A = Ah + Al (fp16 each, ~22 bits), B = fp16 (11 bits);
// C = Ah*B + Al*B  -> error ~2^-12 from B representation only.
// ---------------------------------------------------------------------------
__device__ __forceinline__ uint2 splt2f(float x0, float x1){
    __half2 hp = __float22half2_rn(make_float2(x0, x1));
    float2 hf = __half22float2(hp);
    __half2 lp = __float22half2_rn(make_float2(x0 - hf.x, x1 - hf.y));
    uint2 r;
    r.x = *(unsigned*)&hp;
    r.y = *(unsigned*)&lp;
    return r;
}
__device__ __forceinline__ unsigned pack_f16(float x0, float x1){
    __half2 hp = __float22half2_rn(make_float2(x0, x1));
    return *(unsigned*)&hp;
}
__device__ __forceinline__ void mma_f16(float* d, const unsigned* a, const unsigned* b){
    asm volatile(
        "mma.sync.aligned.m16n8k16.row.col.f32.f16.f16.f32 "
        "{%0,%1,%2,%3}, {%4,%5,%6,%7}, {%8,%9}, {%0,%1,%2,%3};"
        : "+f"(d[0]), "+f"(d[1]), "+f"(d[2]), "+f"(d[3])
        : "r"(a[0]), "r"(a[1]), "r"(a[2]), "r"(a[3]),
          "r"(b[0]), "r"(b[1]));
}
__device__ __forceinline__ unsigned s2u(const void* p){
    return (unsigned)__cvta_generic_to_shared(p);
}
__device__ __forceinline__ void cpa16(unsigned sdst, const void* gsrc){
    asm volatile("cp.async.ca.shared.global [%0], [%1], 16;" :: "r"(sdst), "l"(gsrc));
}
#define CP_COMMIT() asm volatile("cp.async.commit_group;")
#define CP_WAIT1()  asm volatile("cp.async.wait_group 1;" ::: "memory")
#define CP_WAIT0()  asm volatile("cp.async.wait_group 0;" ::: "memory")

// ---------------------------------------------------------------------------
// K0: pre-split X into fp16 {hi,lo} pairs; Wq/Wv into single fp16 planes.
// grid 544: [0,512) -> X (16 floats/thread), [512,528) -> Wq, [528,544) -> Wv.
// ---------------------------------------------------------------------------
__global__ __launch_bounds__(256) void presplit_kernel(
    const float* __restrict__ X,
    const float* __restrict__ Wq,
    const float* __restrict__ Wv)
{
    int bid = blockIdx.x;
    if (bid < 512) {
        int tl = bid*256 + threadIdx.x;
        size_t f0 = (size_t)tl * 16;
        #pragma unroll
        for (int c = 0; c < 2; c++) {
            float4 a = *(const float4*)(X + f0 + c*8);
            float4 b = *(const float4*)(X + f0 + c*8 + 4);
            uint2 p0 = splt2f(a.x, a.y), p1 = splt2f(a.z, a.w);
            uint2 p2 = splt2f(b.x, b.y), p3 = splt2f(b.z, b.w);
            *(uint4*)(g_xs + f0/2 + c*4)     = make_uint4(p0.x, p0.y, p1.x, p1.y);
            *(uint4*)(g_xs + f0/2 + c*4 + 2) = make_uint4(p2.x, p2.y, p3.x, p3.y);
        }
    } else {
        const float* src = (bid < 528) ? Wq : Wv;
        unsigned* dst    = (bid < 528) ? g_wq1 : g_wv1;
        int tl = ((bid - 512) & 15)*256 + threadIdx.x;
        size_t f0 = (size_t)tl * 16;
        #pragma unroll
        for (int c = 0; c < 2; c++) {
            float4 a = *(const float4*)(src + f0 + c*8);
            float4 b = *(const float4*)(src + f0 + c*8 + 4);
            *(uint4*)(dst + f0/2 + c*4) = make_uint4(
                pack_f16(a.x, a.y), pack_f16(a.z, a.w),
                pack_f16(b.x, b.y), pack_f16(b.z, b.w));
        }
    }
}

// ---------------------------------------------------------------------------
// GEMM tiles (per k16 slab): A uint2[128][12] (pairs, pitch 12) = 12288 B;
// B unsigned[rows][12] (pitch 12) = rows*48 B. 3-stage cp.async pipeline,
// one __syncthreads per slab.
// ---------------------------------------------------------------------------
#define QSTG   18432           // qv: A 12288 + Bq 3072 + Bv 3072
#define QV_SMEM (3*QSTG)
#define OSTG   15360           // out: A 12288 + B 3072
#define OUT_SMEM (3*OSTG)
// stage-internal offsets (bytes)
#define OFF_A   0
#define OFF_B0  12288      // qv: Bq, out: B
#define OFF_B1  15360      // qv: Bv

// A fragments: aH/aL[2][4] from uint2 tile at pair-index tg, tg+4
#define LOAD_A(AT)                                                            \
    _Pragma("unroll")                                                         \
    for (int mi = 0; mi < 2; mi++) {                                          \
        int r = wm*32 + mi*16 + g;                                            \
        uint2 q;                                                              \
        q = (AT)[(r  )*12 + tg  ]; aH[mi][0]=q.x; aL[mi][0]=q.y;              \
        q = (AT)[(r+8)*12 + tg  ]; aH[mi][1]=q.x; aL[mi][1]=q.y;              \
        q = (AT)[(r  )*12 + tg+4]; aH[mi][2]=q.x; aL[mi][2]=q.y;              \
        q = (AT)[(r+8)*12 + tg+4]; aH[mi][3]=q.x; aL[mi][3]=q.y;              \
    }

// ---------------------------------------------------------------------------
// K1: fused Q+V projection + bias + RoPE. BM=128 BN=64 BK=16, 256 threads,
// 8 warps (4m x 2n), warp tile 32x32. grid (64, 4). (R15 verbatim.)
// ---------------------------------------------------------------------------
__global__ __launch_bounds__(256, 2) void qv2_tc(
    const float* __restrict__ bq, const float* __restrict__ bv)
{
    extern __shared__ __align__(16) char dyn[];
    const unsigned smb = s2u(dyn);
    const int t = threadIdx.x;
    const int lane = t & 31, warp = t >> 5;
    const int g = lane >> 2, tg = lane & 3;
    const int wm = warp & 3, wn = warp >> 2;
    const int m0 = blockIdx.x * 128;
    const int nb = blockIdx.y * 64;

    float accQ[2][4][4] = {};
    float accV[2][4][4] = {};

    #define QV_ISSUE(s_, kt_) do {                                              \
        unsigned sb_ = smb + (s_)*QSTG;                                         \
        int kb_ = (kt_)*8;                                                      \
        _Pragma("unroll")                                                       \
        for (int i = 0; i < 2; i++) {                                           \
            int id = t + i*256;                                                 \
            int row = id >> 2, j0 = (id & 3) * 2;                               \
            cpa16(sb_ + OFF_A + (unsigned)(row*96 + j0*8),                      \
                  g_xs + (size_t)(m0+row)*128 + kb_ + j0);                      \
        }                                                                       \
        {                                                                       \
            int rr = t & 127;                                                   \
            int row = rr >> 1, ch = rr & 1;                                     \
            const unsigned* W1 = (t < 128) ? g_wq1 : g_wv1;                     \
            unsigned dofs = (t < 128) ? OFF_B0 : OFF_B1;                        \
            cpa16(sb_ + dofs + (unsigned)(row*48 + ch*16),                      \
                  W1 + (size_t)(nb+row)*128 + kb_ + ch*4);                      \
        }                                                                       \
        CP_COMMIT();                                                            \
    } while (0)

    QV_ISSUE(0, 0);
    QV_ISSUE(1, 1);

    #pragma unroll
    for (int it = 0; it < 16; it++) {
        const int cur = it % 3;
        if (it < 15) { CP_WAIT1(); } else { CP_WAIT0(); }
        __syncthreads();
        if (it + 2 < 16) { QV_ISSUE((it+2)%3, it+2); }
        {
            const uint2*    AT = (const uint2*)(dyn + cur*QSTG + OFF_A);
            const unsigned* BQ = (const unsigned*)(dyn + cur*QSTG + OFF_B0);
            const unsigned* BV = (const unsigned*)(dyn + cur*QSTG + OFF_B1);
            unsigned aH[2][4], aL[2][4], bF[4][2];
            LOAD_A(AT);
            #pragma unroll
            for (int ni = 0; ni < 4; ni++) {
                int nn = wn*32 + ni*8 + g;
                bF[ni][0] = BQ[nn*12 + tg];
                bF[ni][1] = BQ[nn*12 + tg+4];
            }
            #pragma unroll
            for (int mi = 0; mi < 2; mi++)
                #pragma unroll
                for (int ni = 0; ni < 4; ni++) mma_f16(accQ[mi][ni], aH[mi], bF[ni]);
            #pragma unroll
            for (int mi = 0; mi < 2; mi++)
                #pragma unroll
                for (int ni = 0; ni < 4; ni++) mma_f16(accQ[mi][ni], aL[mi], bF[ni]);
            #pragma unroll
            for (int ni = 0; ni < 4; ni++) {
                int nn = wn*32 + ni*8 + g;
                bF[ni][0] = BV[nn*12 + tg];
                bF[ni][1] = BV[nn*12 + tg+4];
            }
            #pragma unroll
            for (int mi = 0; mi < 2; mi++)
                #pragma unroll
                for (int ni = 0; ni < 4; ni++) mma_f16(accV[mi][ni], aH[mi], bF[ni]);
            #pragma unroll
            for (int mi = 0; mi < 2; mi++)
                #pragma unroll
                for (int ni = 0; ni < 4; ni++) mma_f16(accV[mi][ni], aL[mi], bF[ni]);
        }
    }
    #undef QV_ISSUE

    // Epilogue: bias + RoPE; write fp16 split pairs.
    const float th = (nb < 128) ? 1.0f : 1e-4f;
    #pragma unroll
    for (int mi = 0; mi < 2; mi++) {
        #pragma unroll
        for (int half = 0; half < 2; half++) {
            int r = m0 + wm*32 + mi*16 + g + half*8;
            float pos = (float)((r & (S_-1)) + 1);     // 1-indexed position
            float sv, cv; sincosf(pos * th, &sv, &cv);
            #pragma unroll
            for (int ni = 0; ni < 4; ni++) {
                int d = nb + wn*32 + ni*8 + 2*tg;
                size_t pi = (size_t)r*128 + d/2;
                float xe, xo;
                xe = accQ[mi][ni][half*2+0] + bq[d];
                xo = accQ[mi][ni][half*2+1] + bq[d+1];
                g_xqs[pi] = splt2f(xe*sv - xo*cv, xe*cv + xo*sv);
                xe = accV[mi][ni][half*2+0] + bv[d];
                xo = accV[mi][ni][half*2+1] + bv[d+1];
                g_xvs[pi] = splt2f(xe*sv - xo*cv, xe*cv + xo*sv);
            }
        }
    }
}

// ---------------------------------------------------------------------------
// K2 (fused): per (b,h): M[e][f] = (1/4) * sum_s xq[..e]*xv[..f], then
// W2T[b][n][16h+e] = sum_f M[e][f]*wo[n][16h+f], stored single fp16 plane.
// xq/xv reconstructed from fp16 {hi,lo} pairs (f32 = hi + lo, ~22 bits).
// ---------------------------------------------------------------------------
__global__ __launch_bounds__(256) void mw_kernel(const float* __restrict__ Wo)
{
    __shared__ __align__(16) char smem_raw[38912];
    float (*qs)[20]       = (float(*)[20])(smem_raw);
    float (*vs)[20]       = (float(*)[20])(smem_raw + 10240);
    float (*part)[16][17] = (float(*)[16][17])(smem_raw + 20480);
    float (*wos)[20]      = (float(*)[20])(smem_raw);            // phase2 overlay
    __shared__ float Ms[16][16];

    const int bh = blockIdx.x, b = bh >> 4, h = bh & 15;
    const int t = threadIdx.x;
    const int grp = t >> 4, lt = t & 15;
    const int e4 = (lt >> 2) * 4, f4 = (lt & 3) * 4;
    float c[4][4] = {};

    const int lrow = t & 127, larr = t >> 7;   // 1 thread = 1 row of q or v
    const uint2* P = larr ? g_xvs : g_xqs;

    for (int chunk = 0; chunk < 8; chunk++) {
        int sb = chunk * 128;
        {
            size_t gro = (size_t)(b*S_ + sb + lrow)*128 + h*8;
            float* dr = larr ? vs[lrow] : qs[lrow];
            #pragma unroll
            for (int j = 0; j < 8; j += 2) {
                uint4 two = *(const uint4*)(P + gro + j);   // 2 uint2 pairs
                float2 h0 = __half22float2(*(const __half2*)&two.x);
                float2 l0 = __half22float2(*(const __half2*)&two.y);
                float2 h1 = __half22float2(*(const __half2*)&two.z);
                float2 l1 = __half22float2(*(const __half2*)&two.w);
                dr[2*j+0] = h0.x + l0.x;  dr[2*j+1] = h0.y + l0.y;
                dr[2*j+2] = h1.x + l1.x;  dr[2*j+3] = h1.y + l1.y;
            }
        }
        __syncthreads();
        int r0 = grp * 8;
        #pragma unroll
        for (int ss = 0; ss < 8; ss++) {
            float4 q4 = *(const float4*)&qs[r0+ss][e4];
            float4 v4 = *(const float4*)&vs[r0+ss][f4];
            c[0][0] += q4.x*v4.x; c[0][1] += q4.x*v4.y; c[0][2] += q4.x*v4.z; c[0][3] += q4.x*v4.w;
            c[1][0] += q4.y*v4.x; c[1][1] += q4.y*v4.y; c[1][2] += q4.y*v4.z; c[1][3] += q4.y*v4.w;
            c[2][0] += q4.z*v4.x; c[2][1] += q4.z*v4.y; c[2][2] += q4.z*v4.z; c[2][3] += q4.z*v4.w;
            c[3][0] += q4.w*v4.x; c[3][1] += q4.w*v4.y; c[3][2] += q4.w*v4.z; c[3][3] += q4.w*v4.w;
        }
        __syncthreads();
    }
    #pragma unroll
    for (int i = 0; i < 4; i++)
        #pragma unroll
        for (int j = 0; j < 4; j++)
            part[grp][e4+i][f4+j] = c[i][j];
    __syncthreads();
    {
        int e = t >> 4, f = t & 15;
        float s = 0.f;
        #pragma unroll
        for (int gg = 0; gg < 16; gg++) s += part[gg][e][f];
        __syncthreads();                 // all part reads done before wos overwrite
        Ms[e][f] = s * 0.25f;            // 1/sqrt(HD=16)
    }
    #pragma unroll
    for (int i = 0; i < 4; i++) {
        int idx = t + i*256;
        int row = idx >> 2, c4 = (idx & 3) * 4;
        *(float4*)&wos[row][c4] = *(const float4*)(Wo + (size_t)row*D_ + h*16 + c4);
    }
    __syncthreads();
    const int n = t;
    float vals[16];
    #pragma unroll
    for (int e = 0; e < 16; e++) {
        float a = 0.f;
        #pragma unroll
        for (int f = 0; f < 16; f++) a += Ms[e][f] * wos[n][f];
        vals[e] = a;
    }
    size_t obase = ((size_t)b*D_ + n)*128 + h*8;   // pair index
    #pragma unroll
    for (int e = 0; e < 16; e += 2)
        g_w2f[obase + e/2] = pack_f16(vals[e], vals[e+1]);
}

// ---------------------------------------------------------------------------
// K3: out_b = xq_b @ W2T_b^T + bo. BM=128 BN=64 BK=16, 256 threads,
// 8 warps (4m x 2n), warp tile 32x32. grid (4, 8, 8) = 256 CTAs, 3 CTAs/SM.
// ---------------------------------------------------------------------------
__global__ __launch_bounds__(256, 3) void out_tc(
    const float* __restrict__ bo, float* __restrict__ out)
{
    extern __shared__ __align__(16) char dyn2[];
    const unsigned smb = s2u(dyn2);
    const int t = threadIdx.x;
    const int lane = t & 31, warp = t >> 5;
    const int g = lane >> 2, tg = lane & 3;
    const int wm = warp & 3, wn = warp >> 2;
    const int bz = blockIdx.z;
    const int m0 = blockIdx.y * 128, n0 = blockIdx.x * 64;
    const int ra0 = bz*S_ + m0;
    const int rb0 = bz*D_ + n0;

    float acc[2][4][4] = {};

    // Per slab: A 512 cp.async (2/thread), B 128 (half threads).
    #define OUT_ISSUE(s_, kt_) do {                                             \
        unsigned sb_ = smb + (s_)*OSTG;                                         \
        int kb_ = (kt_)*8;                                                      \
        _Pragma("unroll")                                                       \
        for (int i = 0; i < 2; i++) {                                           \
            int id = t + i*256;                                                 \
            int row = id >> 2, j0 = (id & 3) * 2;                               \
            cpa16(sb_ + OFF_A + (unsigned)(row*96 + j0*8),                      \
                  g_xqs + (size_t)(ra0+row)*128 + kb_ + j0);                    \
        }                                                                       \
        if (t < 128) {                                                          \
            int row = t >> 1, ch = t & 1;                                       \
            cpa16(sb_ + OFF_B0 + (unsigned)(row*48 + ch*16),                    \
                  g_w2f + (size_t)(rb0+row)*128 + kb_ + ch*4);                  \
        }                                                                       \
        CP_COMMIT();                                                            \
    } while (0)

    OUT_ISSUE(0, 0);
    OUT_ISSUE(1, 1);

    #pragma unroll
    for (int it = 0; it < 16; it++) {
        const int cur = it % 3;
        if (it < 15) { CP_WAIT1(); } else { CP_WAIT0(); }
        __syncthreads();
        if (it + 2 < 16) { OUT_ISSUE((it+2)%3, it+2); }
        {
            const uint2*    AT = (const uint2*)(dyn2 + cur*OSTG + OFF_A);
            const unsigned* BT = (const unsigned*)(dyn2 + cur*OSTG + OFF_B0);
            unsigned aH[2][4], aL[2][4], bF[4][2];
            LOAD_A(AT);
            #pragma unroll
            for (int ni = 0; ni < 4; ni++) {
                int nn = wn*32 + ni*8 + g;
                bF[ni][0] = BT[nn*12 + tg];
                bF[ni][1] = BT[nn*12 + tg+4];
            }
            #pragma unroll
            for (int mi = 0; mi < 2; mi++)
                #pragma unroll
                for (int ni = 0; ni < 4; ni++) mma_f16(acc[mi][ni], aH[mi], bF[ni]);
            #pragma unroll
            for (int mi = 0; mi < 2; mi++)
                #pragma unroll
                for (int ni = 0; ni < 4; ni++) mma_f16(acc[mi][ni], aL[mi], bF[ni]);
        }
    }
    #undef OUT_ISSUE

    #pragma unroll
    for (int mi = 0; mi < 2; mi++) {
        #pragma unroll
        for (int half = 0; half < 2; half++) {
            int r = bz*S_ + m0 + wm*32 + mi*16 + g + half*8;
            #pragma unroll
            for (int ni = 0; ni < 4; ni++) {
                int d = n0 + wn*32 + ni*8 + 2*tg;
                float2 o = make_float2(acc[mi][ni][half*2+0] + bo[d],
                                       acc[mi][ni][half*2+1] + bo[d+1]);
                *(float2*)(out + (size_t)r*D_ + d) = o;
            }
        }
    }
}

// ---------------------------------------------------------------------------
extern "C" void kernel_launch(void* const* d_in, const int* in_sizes, int n_in,
                              void* d_out, int out_size)
{
    (void)in_sizes; (void)n_in; (void)out_size;
    const float* x   = (const float*)d_in[0];
    const float* wqw = (const float*)d_in[1];
    const float* wqb = (const float*)d_in[2];
    // d_in[3], d_in[4] = wk_w, wk_b : dead in reference
    const float* wvw = (const float*)d_in[5];
    const float* wvb = (const float*)d_in[6];
    const float* wow = (const float*)d_in[7];
    const float* wob = (const float*)d_in[8];
    float* out = (float*)d_out;

    cudaFuncSetAttribute(qv2_tc, cudaFuncAttributeMaxDynamicSharedMemorySize, QV_SMEM);
    cudaFuncSetAttribute(out_tc, cudaFuncAttributeMaxDynamicSharedMemorySize, OUT_SMEM);

    presplit_kernel<<<544, 256>>>(x, wqw, wvw);
    qv2_tc<<<dim3(64, 4), 256, QV_SMEM>>>(wqb, wvb);
    mw_kernel<<<128, 256>>>(wow);
    out_tc<<<dim3(4, 8, 8), 256, OUT_SMEM>>>(wob, out);
}

// round 17
// speedup vs baseline: 1.0849x; 1.0849x over previous
#include <cuda_runtime.h>
#include <cuda_fp16.h>

// Problem constants
#define B_ 8
#define S_ 1024
#define D_ 256
#define NR (B_*S_)   // 8192 rows

// Scratch (static device allocations — allowed)
// A-side: fp16 {hi,lo} per value-pair -> uint2 {hi_f16x2, lo_f16x2} per k-pair
__device__ __align__(16) uint2    g_xs [NR*128];      // X split
__device__ __align__(16) uint2    g_xqs[NR*128];      // rope(q) split
__device__ __align__(16) uint2    g_xvs[NR*128];      // rope(v) split
// B-side: single fp16 plane, 1 unsigned (f16x2) per k-pair
__device__ __align__(16) unsigned g_wqv[2*D_*128];    // [Wq ; Wv] fp16, rows 0-255 / 256-511
__device__ __align__(16) unsigned g_w2f[B_*D_*128];   // W2^T fp16 [b][n][kpair]

// ---------------------------------------------------------------------------
// fp16 2-term: A = Ah + Al (fp16 each, ~22 bits), B = fp16 (11 bits);
// C = Ah*B + Al*B  -> error ~2^-12 from B representation only.
// ---------------------------------------------------------------------------
__device__ __forceinline__ uint2 splt2f(float x0, float x1){
    __half2 hp = __float22half2_rn(make_float2(x0, x1));
    float2 hf = __half22float2(hp);
    __half2 lp = __float22half2_rn(make_float2(x0 - hf.x, x1 - hf.y));
    uint2 r;
    r.x = *(unsigned*)&hp;
    r.y = *(unsigned*)&lp;
    return r;
}
__device__ __forceinline__ unsigned pack_f16(float x0, float x1){
    __half2 hp = __float22half2_rn(make_float2(x0, x1));
    return *(unsigned*)&hp;
}
__device__ __forceinline__ void mma_f16(float* d, const unsigned* a, const unsigned* b){
    asm volatile(
        "mma.sync.aligned.m16n8k16.row.col.f32.f16.f16.f32 "
        "{%0,%1,%2,%3}, {%4,%5,%6,%7}, {%8,%9}, {%0,%1,%2,%3};"
        : "+f"(d[0]), "+f"(d[1]), "+f"(d[2]), "+f"(d[3])
        : "r"(a[0]), "r"(a[1]), "r"(a[2]), "r"(a[3]),
          "r"(b[0]), "r"(b[1]));
}
__device__ __forceinline__ unsigned s2u(const void* p){
    return (unsigned)__cvta_generic_to_shared(p);
}
__device__ __forceinline__ void cpa16(unsigned sdst, const void* gsrc){
    asm volatile("cp.async.ca.shared.global [%0], [%1], 16;" :: "r"(sdst), "l"(gsrc));
}
#define CP_COMMIT() asm volatile("cp.async.commit_group;")
#define CP_WAIT1()  asm volatile("cp.async.wait_group 1;" ::: "memory")
#define CP_WAIT0()  asm volatile("cp.async.wait_group 0;" ::: "memory")

// ---------------------------------------------------------------------------
// K0: pre-split X into fp16 {hi,lo} pairs; pack Wq/Wv into merged fp16 plane.
// grid 544: [0,512) -> X, [512,528) -> Wq (rows 0-255), [528,544) -> Wv (+256).
// ---------------------------------------------------------------------------
__global__ __launch_bounds__(256) void presplit_kernel(
    const float* __restrict__ X,
    const float* __restrict__ Wq,
    const float* __restrict__ Wv)
{
    int bid = blockIdx.x;
    if (bid < 512) {
        int tl = bid*256 + threadIdx.x;
        size_t f0 = (size_t)tl * 16;
        #pragma unroll
        for (int c = 0; c < 2; c++) {
            float4 a = *(const float4*)(X + f0 + c*8);
            float4 b = *(const float4*)(X + f0 + c*8 + 4);
            uint2 p0 = splt2f(a.x, a.y), p1 = splt2f(a.z, a.w);
            uint2 p2 = splt2f(b.x, b.y), p3 = splt2f(b.z, b.w);
            *(uint4*)(g_xs + f0/2 + c*4)     = make_uint4(p0.x, p0.y, p1.x, p1.y);
            *(uint4*)(g_xs + f0/2 + c*4 + 2) = make_uint4(p2.x, p2.y, p3.x, p3.y);
        }
    } else {
        const float* src = (bid < 528) ? Wq : Wv;
        unsigned* dst    = g_wqv + ((bid < 528) ? 0 : (size_t)D_*128);
        int tl = ((bid - 512) & 15)*256 + threadIdx.x;
        size_t f0 = (size_t)tl * 16;
        #pragma unroll
        for (int c = 0; c < 2; c++) {
            float4 a = *(const float4*)(src + f0 + c*8);
            float4 b = *(const float4*)(src + f0 + c*8 + 4);
            *(uint4*)(dst + f0/2 + c*4) = make_uint4(
                pack_f16(a.x, a.y), pack_f16(a.z, a.w),
                pack_f16(b.x, b.y), pack_f16(b.z, b.w));
        }
    }
}

// ---------------------------------------------------------------------------
// Unified GEMM geometry (R15 out_tc, the measured optimum):
// BM=128 BN=128 BK=16, 8 warps (4m x 2n), warp tile 32x64,
// 32 MMAs/warp/slab in one run. Stage: A 12288 B + B 6144 B = 18432;
// 3 stages = 55296 -> 2 CTAs/SM. One __syncthreads per slab.
// ---------------------------------------------------------------------------
#define STG   18432
#define GSMEM (3*STG)
#define OFF_A   0
#define OFF_B0  12288

// A fragments: aH/aL[2][4] from uint2 tile at pair-index tg, tg+4
#define LOAD_A(AT)                                                            \
    _Pragma("unroll")                                                         \
    for (int mi = 0; mi < 2; mi++) {                                          \
        int r = wm*32 + mi*16 + g;                                            \
        uint2 q;                                                              \
        q = (AT)[(r  )*12 + tg  ]; aH[mi][0]=q.x; aL[mi][0]=q.y;              \
        q = (AT)[(r+8)*12 + tg  ]; aH[mi][1]=q.x; aL[mi][1]=q.y;              \
        q = (AT)[(r  )*12 + tg+4]; aH[mi][2]=q.x; aL[mi][2]=q.y;              \
        q = (AT)[(r+8)*12 + tg+4]; aH[mi][3]=q.x; aL[mi][3]=q.y;              \
    }

// Issue one slab: A 512 cp.async (2/thread), B 256 (1/thread).
#define SLAB_ISSUE(s_, kt_, Asrc, Bsrc, arow, brow) do {                      \
    unsigned sb_ = smb + (s_)*STG;                                            \
    int kb_ = (kt_)*8;                                                        \
    _Pragma("unroll")                                                         \
    for (int i = 0; i < 2; i++) {                                             \
        int id = t + i*256;                                                   \
        int row = id >> 2, j0 = (id & 3) * 2;                                 \
        cpa16(sb_ + OFF_A + (unsigned)(row*96 + j0*8),                        \
              (Asrc) + (size_t)((arow)+row)*128 + kb_ + j0);                  \
    }                                                                         \
    {                                                                         \
        int row = t >> 1, ch = t & 1;                                         \
        cpa16(sb_ + OFF_B0 + (unsigned)(row*48 + ch*16),                      \
              (Bsrc) + (size_t)((brow)+row)*128 + kb_ + ch*4);                \
    }                                                                         \
    CP_COMMIT();                                                              \
} while (0)

// Mainloop body: fragments + 32 MMAs (2 terms x 2mi x 8ni)
#define SLAB_COMPUTE(base)                                                    \
    {                                                                         \
        const uint2*    AT = (const uint2*)((base) + OFF_A);                  \
        const unsigned* BT = (const unsigned*)((base) + OFF_B0);              \
        unsigned aH[2][4], aL[2][4], bF[8][2];                                \
        LOAD_A(AT);                                                           \
        _Pragma("unroll")                                                     \
        for (int ni = 0; ni < 8; ni++) {                                      \
            int nn = wn*64 + ni*8 + g;                                        \
            bF[ni][0] = BT[nn*12 + tg];                                       \
            bF[ni][1] = BT[nn*12 + tg+4];                                     \
        }                                                                     \
        _Pragma("unroll")                                                     \
        for (int mi = 0; mi < 2; mi++)                                        \
            _Pragma("unroll")                                                 \
            for (int ni = 0; ni < 8; ni++) mma_f16(acc[mi][ni], aH[mi], bF[ni]); \
        _Pragma("unroll")                                                     \
        for (int mi = 0; mi < 2; mi++)                                        \
            _Pragma("unroll")                                                 \
            for (int ni = 0; ni < 8; ni++) mma_f16(acc[mi][ni], aL[mi], bF[ni]); \
    }

// ---------------------------------------------------------------------------
// K1: fused Q+V projection as ONE GEMM vs merged [Wq;Wv] (512 cols) + RoPE.
// grid (64, 4): x = m-block, y = col-block (128 cols, entirely Q or V).
// ---------------------------------------------------------------------------
__global__ __launch_bounds__(256, 2) void qv_tc(
    const float* __restrict__ bq, const float* __restrict__ bv)
{
    extern __shared__ __align__(16) char dyn[];
    const unsigned smb = s2u(dyn);
    const int t = threadIdx.x;
    const int lane = t & 31, warp = t >> 5;
    const int g = lane >> 2, tg = lane & 3;
    const int wm = warp & 3, wn = warp >> 2;
    const int m0 = blockIdx.x * 128;
    const int nbc = blockIdx.y * 128;        // merged col base: 0,128,256,384
    const int isV = nbc >= 256;
    const int nb  = nbc & 255;               // col base within Q or V

    float acc[2][8][4] = {};

    SLAB_ISSUE(0, 0, g_xs, g_wqv, m0, nbc);
    SLAB_ISSUE(1, 1, g_xs, g_wqv, m0, nbc);

    #pragma unroll
    for (int it = 0; it < 16; it++) {
        const int cur = it % 3;
        if (it < 15) { CP_WAIT1(); } else { CP_WAIT0(); }
        __syncthreads();
        if (it + 2 < 16) SLAB_ISSUE((it+2)%3, it+2, g_xs, g_wqv, m0, nbc);
        SLAB_COMPUTE(dyn + cur*STG);
    }

    // Epilogue: bias + RoPE; write fp16 split pairs to xq or xv planes.
    const float th = (nb < 128) ? 1.0f : 1e-4f;
    const float* bias = isV ? bv : bq;
    uint2* dst = isV ? g_xvs : g_xqs;
    #pragma unroll
    for (int mi = 0; mi < 2; mi++) {
        #pragma unroll
        for (int half = 0; half < 2; half++) {
            int r = m0 + wm*32 + mi*16 + g + half*8;
            float pos = (float)((r & (S_-1)) + 1);     // 1-indexed position
            float sv, cv; sincosf(pos * th, &sv, &cv);
            #pragma unroll
            for (int ni = 0; ni < 8; ni++) {
                int d = nb + wn*64 + ni*8 + 2*tg;
                float xe = acc[mi][ni][half*2+0] + bias[d];
                float xo = acc[mi][ni][half*2+1] + bias[d+1];
                dst[(size_t)r*128 + d/2] = splt2f(xe*sv - xo*cv, xe*cv + xo*sv);
            }
        }
    }
}

// ---------------------------------------------------------------------------
// K2 (fused): per (b,h): M[e][f] = (1/4) * sum_s xq[..e]*xv[..f], then
// W2T[b][n][16h+e] = sum_f M[e][f]*wo[n][16h+f], stored single fp16 plane.
// xq/xv reconstructed from fp16 {hi,lo} pairs (f32 = hi + lo, ~22 bits).
// ---------------------------------------------------------------------------
__global__ __launch_bounds__(256) void mw_kernel(const float* __restrict__ Wo)
{
    __shared__ __align__(16) char smem_raw[38912];
    float (*qs)[20]       = (float(*)[20])(smem_raw);
    float (*vs)[20]       = (float(*)[20])(smem_raw + 10240);
    float (*part)[16][17] = (float(*)[16][17])(smem_raw + 20480);
    float (*wos)[20]      = (float(*)[20])(smem_raw);            // phase2 overlay
    __shared__ float Ms[16][16];

    const int bh = blockIdx.x, b = bh >> 4, h = bh & 15;
    const int t = threadIdx.x;
    const int grp = t >> 4, lt = t & 15;
    const int e4 = (lt >> 2) * 4, f4 = (lt & 3) * 4;
    float c[4][4] = {};

    const int lrow = t & 127, larr = t >> 7;   // 1 thread = 1 row of q or v
    const uint2* P = larr ? g_xvs : g_xqs;

    for (int chunk = 0; chunk < 8; chunk++) {
        int sb = chunk * 128;
        {
            size_t gro = (size_t)(b*S_ + sb + lrow)*128 + h*8;
            float* dr = larr ? vs[lrow] : qs[lrow];
            #pragma unroll
            for (int j = 0; j < 8; j += 2) {
                uint4 two = *(const uint4*)(P + gro + j);   // 2 uint2 pairs
                float2 h0 = __half22float2(*(const __half2*)&two.x);
                float2 l0 = __half22float2(*(const __half2*)&two.y);
                float2 h1 = __half22float2(*(const __half2*)&two.z);
                float2 l1 = __half22float2(*(const __half2*)&two.w);
                dr[2*j+0] = h0.x + l0.x;  dr[2*j+1] = h0.y + l0.y;
                dr[2*j+2] = h1.x + l1.x;  dr[2*j+3] = h1.y + l1.y;
            }
        }
        __syncthreads();
        int r0 = grp * 8;
        #pragma unroll
        for (int ss = 0; ss < 8; ss++) {
            float4 q4 = *(const float4*)&qs[r0+ss][e4];
            float4 v4 = *(const float4*)&vs[r0+ss][f4];
            c[0][0] += q4.x*v4.x; c[0][1] += q4.x*v4.y; c[0][2] += q4.x*v4.z; c[0][3] += q4.x*v4.w;
            c[1][0] += q4.y*v4.x; c[1][1] += q4.y*v4.y; c[1][2] += q4.y*v4.z; c[1][3] += q4.y*v4.w;
            c[2][0] += q4.z*v4.x; c[2][1] += q4.z*v4.y; c[2][2] += q4.z*v4.z; c[2][3] += q4.z*v4.w;
            c[3][0] += q4.w*v4.x; c[3][1] += q4.w*v4.y; c[3][2] += q4.w*v4.z; c[3][3] += q4.w*v4.w;
        }
        __syncthreads();
    }
    #pragma unroll
    for (int i = 0; i < 4; i++)
        #pragma unroll
        for (int j = 0; j < 4; j++)
            part[grp][e4+i][f4+j] = c[i][j];
    __syncthreads();
    {
        int e = t >> 4, f = t & 15;
        float s = 0.f;
        #pragma unroll
        for (int gg = 0; gg < 16; gg++) s += part[gg][e][f];
        __syncthreads();                 // all part reads done before wos overwrite
        Ms[e][f] = s * 0.25f;            // 1/sqrt(HD=16)
    }
    #pragma unroll
    for (int i = 0; i < 4; i++) {
        int idx = t + i*256;
        int row = idx >> 2, c4 = (idx & 3) * 4;
        *(float4*)&wos[row][c4] = *(const float4*)(Wo + (size_t)row*D_ + h*16 + c4);
    }
    __syncthreads();
    const int n = t;
    float vals[16];
    #pragma unroll
    for (int e = 0; e < 16; e++) {
        float a = 0.f;
        #pragma unroll
        for (int f = 0; f < 16; f++) a += Ms[e][f] * wos[n][f];
        vals[e] = a;
    }
    size_t obase = ((size_t)b*D_ + n)*128 + h*8;   // pair index
    #pragma unroll
    for (int e = 0; e < 16; e += 2)
        g_w2f[obase + e/2] = pack_f16(vals[e], vals[e+1]);
}

// ---------------------------------------------------------------------------
// K3: out_b = xq_b @ W2T_b^T + bo. BM=128 BN=128 BK=16, warp tile 32x64.
// grid (2, 8, 8). (R15 verbatim — the measured optimum.)
// ---------------------------------------------------------------------------
__global__ __launch_bounds__(256, 2) void out_tc(
    const float* __restrict__ bo, float* __restrict__ out)
{
    extern __shared__ __align__(16) char dyn2[];
    const unsigned smb = s2u(dyn2);
    const int t = threadIdx.x;
    const int lane = t & 31, warp = t >> 5;
    const int g = lane >> 2, tg = lane & 3;
    const int wm = warp & 3, wn = warp >> 2;
    const int bz = blockIdx.z;
    const int m0 = blockIdx.y * 128, n0 = blockIdx.x * 128;
    const int ra0 = bz*S_ + m0;
    const int rb0 = bz*D_ + n0;

    float acc[2][8][4] = {};

    SLAB_ISSUE(0, 0, g_xqs, g_w2f, ra0, rb0);
    SLAB_ISSUE(1, 1, g_xqs, g_w2f, ra0, rb0);

    #pragma unroll
    for (int it = 0; it < 16; it++) {
        const int cur = it % 3;
        if (it < 15) { CP_WAIT1(); } else { CP_WAIT0(); }
        __syncthreads();
        if (it + 2 < 16) SLAB_ISSUE((it+2)%3, it+2, g_xqs, g_w2f, ra0, rb0);
        SLAB_COMPUTE(dyn2 + cur*STG);
    }

    #pragma unroll
    for (int mi = 0; mi < 2; mi++) {
        #pragma unroll
        for (int half = 0; half < 2; half++) {
            int r = bz*S_ + m0 + wm*32 + mi*16 + g + half*8;
            #pragma unroll
            for (int ni = 0; ni < 8; ni++) {
                int d = n0 + wn*64 + ni*8 + 2*tg;
                float2 o = make_float2(acc[mi][ni][half*2+0] + bo[d],
                                       acc[mi][ni][half*2+1] + bo[d+1]);
                *(float2*)(out + (size_t)r*D_ + d) = o;
            }
        }
    }
}

// ---------------------------------------------------------------------------
extern "C" void kernel_launch(void* const* d_in, const int* in_sizes, int n_in,
                              void* d_out, int out_size)
{
    (void)in_sizes; (void)n_in; (void)out_size;
    const float* x   = (const float*)d_in[0];
    const float* wqw = (const float*)d_in[1];
    const float* wqb = (const float*)d_in[2];
    // d_in[3], d_in[4] = wk_w, wk_b : dead in reference
    const float* wvw = (const float*)d_in[5];
    const float* wvb = (const float*)d_in[6];
    const float* wow = (const float*)d_in[7];
    const float* wob = (const float*)d_in[8];
    float* out = (float*)d_out;

    cudaFuncSetAttribute(qv_tc,  cudaFuncAttributeMaxDynamicSharedMemorySize, GSMEM);
    cudaFuncSetAttribute(out_tc, cudaFuncAttributeMaxDynamicSharedMemorySize, GSMEM);

    presplit_kernel<<<544, 256>>>(x, wqw, wvw);
    qv_tc<<<dim3(64, 4), 256, GSMEM>>>(wqb, wvb);
    mw_kernel<<<128, 256>>>(wow);
    out_tc<<<dim3(2, 8, 8), 256, GSMEM>>>(wob, out);
}